// round 15
// baseline (speedup 1.0000x reference)
#include <cuda_runtime.h>
#include <cstdint>

// PrototypeLoss: loss = 1 - (1/B) * sum_c || sum_{i: label_i=c} normalize(f_i) ||
// B = 262144, D = 256, C = 1000 (fixed shapes)
//
// Two graph nodes:
//   scatter_kernel : bucket row indices by class; counters padded to one per
//                    128B line (spreads ATOMGs across LTS partitions); also
//                    resets the work ticket for the worker kernel.
//   worker_kernel  : 1480 persistent-ish workers (148 SMs x 10 blocks, all
//                    wave-1 resident) steal (class,segment) units (NSEG=8,
//                    8000 units) via a global atomic ticket -> zero wave
//                    quantization, ~1-unit tail. Per unit: warp gathers rows
//                    (coalesced 1KB, __ldcs), warp-shuffle sumsq, rsqrt,
//                    accumulate; partial sums merge via float RED.ADD;
//                    per-class ticket elects norm finisher; global ticket
//                    elects output writer. All state self-resets
//                    (graph-replayable; __device__ globals zeroed at load).

static constexpr int C_CLS   = 1000;
static constexpr int D_DIM   = 256;
static constexpr int CAP     = 1024;   // bucket capacity (expected ~262/class)
static constexpr int NSEG    = 8;      // segments per class
static constexpr int UNITS   = C_CLS * NSEG;   // 8000
static constexpr int CNT_PAD = 32;     // ints per counter line (128B)
static constexpr int NWORK   = 1480;   // 148 x 10 worker blocks

__device__ int      g_cnt[C_CLS * CNT_PAD];  // padded; reset by finisher
__device__ int      g_idx[C_CLS * CAP];
__device__ float    g_sum[C_CLS * D_DIM];    // reset by finisher
__device__ int      g_cdone[C_CLS];          // reset by finisher
__device__ unsigned g_tick;                  // reset by scatter_kernel
__device__ float    g_acc;                   // reset by global finisher
__device__ unsigned g_done;                  // reset by global finisher

// ---------------------------------------------------------------------------
// Scatter: one label per thread, one padded-line atomic per thread.
// int64-vs-int32 probe: LE int64 labels in [0,1000) have all odd 32-bit words
// zero; 64 random int32 labels all being zero has probability ~1e-192.
// Probed words lie in the first 1KB (valid under either dtype).
// Also resets the worker ticket (ordered before worker_kernel in the graph).
// ---------------------------------------------------------------------------
__global__ __launch_bounds__(512) void scatter_kernel(const void* __restrict__ labels,
                                                      int B) {
    __shared__ int s_is64;
    const int* lbl32 = (const int*)labels;
    if (blockIdx.x == 0 && threadIdx.x == 0) g_tick = 0u;   // epoch reset
    if (threadIdx.x < 32) {
        int v = lbl32[2 * threadIdx.x + 1] | lbl32[2 * threadIdx.x + 65];
        unsigned any = __ballot_sync(0xffffffffu, v != 0);
        if (threadIdx.x == 0) s_is64 = (any == 0u) ? 1 : 0;
    }
    __syncthreads();

    int i = blockIdx.x * 512 + threadIdx.x;
    if (i >= B) return;
    int l = s_is64 ? (int)__ldcs((const long long*)labels + i)
                   : __ldcs(lbl32 + i);
    if ((unsigned)l >= (unsigned)C_CLS) return;   // defensive
    int p = atomicAdd(&g_cnt[l * CNT_PAD], 1);
    if (p < CAP) g_idx[l * CAP + p] = i;
}

// ---------------------------------------------------------------------------
// worker_kernel: loop { steal unit u -> class c = u/8, segment s = u%8 }.
// Segment s processes bucket entries e = s + 8*j; warp w (of 4) takes
// j = w mod 4. Each row: 2x float4 per lane (coalesced 1KB, __ldcs),
// warp-shuffle sumsq, rsqrt, accumulate 8 regs/lane. 2-row unroll.
// ---------------------------------------------------------------------------
__global__ __launch_bounds__(128) void worker_kernel(const float* __restrict__ f,
                                                     float* __restrict__ out,
                                                     int B) {
    __shared__ float    sm[4][8][33];   // [warp][slot][lane], padded
    __shared__ int      s_fin;
    __shared__ unsigned s_unit;
    const int warp = threadIdx.x >> 5;
    const int lane = threadIdx.x & 31;

    for (;;) {
        __syncthreads();                 // protects s_unit / sm reuse
        if (threadIdx.x == 0) s_unit = atomicAdd(&g_tick, 1u);
        __syncthreads();
        const unsigned u = s_unit;
        if (u >= (unsigned)UNITS) break;

        const int c   = (int)(u >> 3);   // NSEG == 8
        const int seg = (int)(u & 7u);
        int n = g_cnt[c * CNT_PAD];
        if (n > CAP) n = CAP;

        float a0 = 0.f, a1 = 0.f, a2 = 0.f, a3 = 0.f;
        float a4 = 0.f, a5 = 0.f, a6 = 0.f, a7 = 0.f;
        const int* __restrict__ idx = &g_idx[c * CAP];

        int j = warp;
        for (; seg + ((j + 4) << 3) < n; j += 8) {
            int row0 = idx[seg + (j << 3)];
            int row1 = idx[seg + ((j + 4) << 3)];
            const float4* __restrict__ p0 = (const float4*)(f + (size_t)row0 * D_DIM);
            const float4* __restrict__ p1 = (const float4*)(f + (size_t)row1 * D_DIM);
            float4 x0 = __ldcs(p0 + lane), y0 = __ldcs(p0 + lane + 32);
            float4 x1 = __ldcs(p1 + lane), y1 = __ldcs(p1 + lane + 32);
            float s0 = x0.x*x0.x + x0.y*x0.y + x0.z*x0.z + x0.w*x0.w
                     + y0.x*y0.x + y0.y*y0.y + y0.z*y0.z + y0.w*y0.w;
            float s1 = x1.x*x1.x + x1.y*x1.y + x1.z*x1.z + x1.w*x1.w
                     + y1.x*y1.x + y1.y*y1.y + y1.z*y1.z + y1.w*y1.w;
            #pragma unroll
            for (int o = 16; o; o >>= 1) {
                s0 += __shfl_xor_sync(0xffffffffu, s0, o);
                s1 += __shfl_xor_sync(0xffffffffu, s1, o);
            }
            float i0 = rsqrtf(fmaxf(s0, 1e-24f));
            float i1 = rsqrtf(fmaxf(s1, 1e-24f));
            a0 += x0.x*i0 + x1.x*i1;  a1 += x0.y*i0 + x1.y*i1;
            a2 += x0.z*i0 + x1.z*i1;  a3 += x0.w*i0 + x1.w*i1;
            a4 += y0.x*i0 + y1.x*i1;  a5 += y0.y*i0 + y1.y*i1;
            a6 += y0.z*i0 + y1.z*i1;  a7 += y0.w*i0 + y1.w*i1;
        }
        for (; seg + (j << 3) < n; j += 4) {
            int row = idx[seg + (j << 3)];
            const float4* __restrict__ p = (const float4*)(f + (size_t)row * D_DIM);
            float4 x = __ldcs(p + lane), y = __ldcs(p + lane + 32);
            float s = x.x*x.x + x.y*x.y + x.z*x.z + x.w*x.w
                    + y.x*y.x + y.y*y.y + y.z*y.z + y.w*y.w;
            #pragma unroll
            for (int o = 16; o; o >>= 1) s += __shfl_xor_sync(0xffffffffu, s, o);
            float iv = rsqrtf(fmaxf(s, 1e-24f));
            a0 += x.x*iv; a1 += x.y*iv; a2 += x.z*iv; a3 += x.w*iv;
            a4 += y.x*iv; a5 += y.y*iv; a6 += y.z*iv; a7 += y.w*iv;
        }

        // lane l slot k(0-3) -> element 4l+k ; slots 4-7 -> 128+4l+k
        sm[warp][0][lane] = a0; sm[warp][1][lane] = a1;
        sm[warp][2][lane] = a2; sm[warp][3][lane] = a3;
        sm[warp][4][lane] = a4; sm[warp][5][lane] = a5;
        sm[warp][6][lane] = a6; sm[warp][7][lane] = a7;
        __syncthreads();

        // thread t -> elements t, t+128; combine 4 warps; RED.ADD into g_sum
        {
            int t  = threadIdx.x;                 // 0..127
            int l0 = t >> 2, k0 = t & 3;
            float v0 = sm[0][k0][l0] + sm[1][k0][l0] + sm[2][k0][l0] + sm[3][k0][l0];
            float v1 = sm[0][4 + k0][l0] + sm[1][4 + k0][l0]
                     + sm[2][4 + k0][l0] + sm[3][4 + k0][l0];
            atomicAdd(&g_sum[c * D_DIM + t], v0);
            atomicAdd(&g_sum[c * D_DIM + t + 128], v1);
        }

        __threadfence();
        __syncthreads();
        if (threadIdx.x == 0) {
            int p = atomicAdd(&g_cdone[c], 1);
            s_fin = (p == NSEG - 1) ? 1 : 0;
        }
        __syncthreads();

        if (s_fin) {
            __threadfence();
            int t = threadIdx.x;
            volatile float* gs = g_sum;
            float v0 = gs[c * D_DIM + t];
            float v1 = gs[c * D_DIM + t + 128];
            g_sum[c * D_DIM + t] = 0.f;            // self-reset
            g_sum[c * D_DIM + t + 128] = 0.f;
            float ss = v0 * v0 + v1 * v1;
            #pragma unroll
            for (int o = 16; o; o >>= 1) ss += __shfl_xor_sync(0xffffffffu, ss, o);
            if (lane == 0) sm[0][0][warp] = ss;
            __syncthreads();
            if (threadIdx.x == 0) {
                float tot = sm[0][0][0] + sm[0][0][1] + sm[0][0][2] + sm[0][0][3];
                atomicAdd(&g_acc, sqrtf(tot));
                g_cnt[c * CNT_PAD] = 0;            // self-reset
                g_cdone[c]         = 0;
                __threadfence();
                unsigned q = atomicAdd(&g_done, 1u);
                if (q == (unsigned)(C_CLS - 1)) {
                    __threadfence();
                    float acc = *((volatile float*)&g_acc);
                    out[0] = 1.0f - acc / (float)B;
                    g_acc  = 0.0f;                 // global self-reset
                    g_done = 0u;
                }
            }
        }
    }
}

extern "C" void kernel_launch(void* const* d_in, const int* in_sizes, int n_in,
                              void* d_out, int out_size) {
    const float* features = (const float*)d_in[0];
    const void*  labels   = d_in[1];
    int B = in_sizes[1];                                    // 262144 labels
    if (B * D_DIM != in_sizes[0]) B = in_sizes[0] / D_DIM;  // defensive

    scatter_kernel<<<(B + 511) / 512, 512>>>(labels, B);
    worker_kernel<<<NWORK, 128>>>(features, (float*)d_out, B);
}

// round 16
// speedup vs baseline: 1.0270x; 1.0270x over previous
#include <cuda_runtime.h>
#include <cstdint>

// PrototypeLoss: loss = 1 - (1/B) * sum_c || sum_{i: label_i=c} normalize(f_i) ||
// B = 262144, D = 256, C = 1000 (fixed shapes)
//
// Two graph nodes (proven structure; class kernel now 4-row unrolled for MLP):
//   scatter_kernel : bucket row indices by class; counters padded to one per
//                    128B line (spreads ATOMGs across LTS partitions).
//   class_kernel   : NSEG=8 segment blocks per class (grid 8000, 128 thr);
//                    warp gathers 4 rows per iteration (16 LDG.128 issued
//                    before any math -> ~48KB in flight/SM), warp-shuffle
//                    sumsq, rsqrt, accumulate; partial sums merge via float
//                    RED.ADD; per-class ticket elects norm finisher; global
//                    ticket elects output writer. All state self-resets
//                    (graph-replayable; __device__ globals zeroed at load).

static constexpr int C_CLS   = 1000;
static constexpr int D_DIM   = 256;
static constexpr int CAP     = 1024;   // bucket capacity (expected ~262/class)
static constexpr int NSEG    = 8;      // segment blocks per class
static constexpr int CNT_PAD = 32;     // ints per counter line (128B)

__device__ int      g_cnt[C_CLS * CNT_PAD];  // padded; reset by finisher
__device__ int      g_idx[C_CLS * CAP];
__device__ float    g_sum[C_CLS * D_DIM];    // reset by finisher
__device__ int      g_cdone[C_CLS];          // reset by finisher
__device__ float    g_acc;                   // reset by global finisher
__device__ unsigned g_done;                  // reset by global finisher

// ---------------------------------------------------------------------------
// Scatter: one label per thread, one padded-line atomic per thread.
// int64-vs-int32 probe: LE int64 labels in [0,1000) have all odd 32-bit words
// zero; 64 random int32 labels all being zero has probability ~1e-192.
// Probed words lie in the first 1KB (valid under either dtype).
// ---------------------------------------------------------------------------
__global__ __launch_bounds__(512) void scatter_kernel(const void* __restrict__ labels,
                                                      int B) {
    __shared__ int s_is64;
    const int* lbl32 = (const int*)labels;
    if (threadIdx.x < 32) {
        int v = lbl32[2 * threadIdx.x + 1] | lbl32[2 * threadIdx.x + 65];
        unsigned any = __ballot_sync(0xffffffffu, v != 0);
        if (threadIdx.x == 0) s_is64 = (any == 0u) ? 1 : 0;
    }
    __syncthreads();

    int i = blockIdx.x * 512 + threadIdx.x;
    if (i >= B) return;
    int l = s_is64 ? (int)__ldcs((const long long*)labels + i)
                   : __ldcs(lbl32 + i);
    if ((unsigned)l >= (unsigned)C_CLS) return;   // defensive
    int p = atomicAdd(&g_cnt[l * CNT_PAD], 1);
    if (p < CAP) g_idx[l * CAP + p] = i;
}

// ---------------------------------------------------------------------------
// class_kernel: block b -> class c = b/NSEG, segment s = b%NSEG.
// Segment s processes bucket entries e = s + 8*j; warp w (of 4) takes
// j = w mod 4, stepping 16 with a 4-row unroll. All 16 float4 loads issue
// before any arithmetic (maximize outstanding LDG.128).
// ---------------------------------------------------------------------------
__global__ __launch_bounds__(128) void class_kernel(const float* __restrict__ f,
                                                    float* __restrict__ out,
                                                    int B) {
    __shared__ float sm[4][8][33];   // [warp][slot][lane], padded
    __shared__ int   s_fin;
    const int b    = blockIdx.x;
    const int c    = b >> 3;         // NSEG == 8
    const int seg  = b & 7;
    int n = g_cnt[c * CNT_PAD];
    if (n > CAP) n = CAP;
    const int warp = threadIdx.x >> 5;
    const int lane = threadIdx.x & 31;

    float a0 = 0.f, a1 = 0.f, a2 = 0.f, a3 = 0.f;
    float a4 = 0.f, a5 = 0.f, a6 = 0.f, a7 = 0.f;
    const int* __restrict__ idx = &g_idx[c * CAP];

    int j = warp;
    for (; seg + ((j + 12) << 3) < n; j += 16) {
        int row0 = idx[seg + (j << 3)];
        int row1 = idx[seg + ((j + 4) << 3)];
        int row2 = idx[seg + ((j + 8) << 3)];
        int row3 = idx[seg + ((j + 12) << 3)];
        const float4* __restrict__ p0 = (const float4*)(f + (size_t)row0 * D_DIM);
        const float4* __restrict__ p1 = (const float4*)(f + (size_t)row1 * D_DIM);
        const float4* __restrict__ p2 = (const float4*)(f + (size_t)row2 * D_DIM);
        const float4* __restrict__ p3 = (const float4*)(f + (size_t)row3 * D_DIM);
        // issue all 16 loads before any math
        float4 x0 = __ldcs(p0 + lane), y0 = __ldcs(p0 + lane + 32);
        float4 x1 = __ldcs(p1 + lane), y1 = __ldcs(p1 + lane + 32);
        float4 x2 = __ldcs(p2 + lane), y2 = __ldcs(p2 + lane + 32);
        float4 x3 = __ldcs(p3 + lane), y3 = __ldcs(p3 + lane + 32);
        float s0 = x0.x*x0.x + x0.y*x0.y + x0.z*x0.z + x0.w*x0.w
                 + y0.x*y0.x + y0.y*y0.y + y0.z*y0.z + y0.w*y0.w;
        float s1 = x1.x*x1.x + x1.y*x1.y + x1.z*x1.z + x1.w*x1.w
                 + y1.x*y1.x + y1.y*y1.y + y1.z*y1.z + y1.w*y1.w;
        float s2 = x2.x*x2.x + x2.y*x2.y + x2.z*x2.z + x2.w*x2.w
                 + y2.x*y2.x + y2.y*y2.y + y2.z*y2.z + y2.w*y2.w;
        float s3 = x3.x*x3.x + x3.y*x3.y + x3.z*x3.z + x3.w*x3.w
                 + y3.x*y3.x + y3.y*y3.y + y3.z*y3.z + y3.w*y3.w;
        #pragma unroll
        for (int o = 16; o; o >>= 1) {
            s0 += __shfl_xor_sync(0xffffffffu, s0, o);
            s1 += __shfl_xor_sync(0xffffffffu, s1, o);
            s2 += __shfl_xor_sync(0xffffffffu, s2, o);
            s3 += __shfl_xor_sync(0xffffffffu, s3, o);
        }
        float i0 = rsqrtf(fmaxf(s0, 1e-24f));
        float i1 = rsqrtf(fmaxf(s1, 1e-24f));
        float i2 = rsqrtf(fmaxf(s2, 1e-24f));
        float i3 = rsqrtf(fmaxf(s3, 1e-24f));
        a0 += x0.x*i0 + x1.x*i1 + x2.x*i2 + x3.x*i3;
        a1 += x0.y*i0 + x1.y*i1 + x2.y*i2 + x3.y*i3;
        a2 += x0.z*i0 + x1.z*i1 + x2.z*i2 + x3.z*i3;
        a3 += x0.w*i0 + x1.w*i1 + x2.w*i2 + x3.w*i3;
        a4 += y0.x*i0 + y1.x*i1 + y2.x*i2 + y3.x*i3;
        a5 += y0.y*i0 + y1.y*i1 + y2.y*i2 + y3.y*i3;
        a6 += y0.z*i0 + y1.z*i1 + y2.z*i2 + y3.z*i3;
        a7 += y0.w*i0 + y1.w*i1 + y2.w*i2 + y3.w*i3;
    }
    for (; seg + (j << 3) < n; j += 4) {
        int row = idx[seg + (j << 3)];
        const float4* __restrict__ p = (const float4*)(f + (size_t)row * D_DIM);
        float4 x = __ldcs(p + lane), y = __ldcs(p + lane + 32);
        float s = x.x*x.x + x.y*x.y + x.z*x.z + x.w*x.w
                + y.x*y.x + y.y*y.y + y.z*y.z + y.w*y.w;
        #pragma unroll
        for (int o = 16; o; o >>= 1) s += __shfl_xor_sync(0xffffffffu, s, o);
        float iv = rsqrtf(fmaxf(s, 1e-24f));
        a0 += x.x*iv; a1 += x.y*iv; a2 += x.z*iv; a3 += x.w*iv;
        a4 += y.x*iv; a5 += y.y*iv; a6 += y.z*iv; a7 += y.w*iv;
    }

    // lane l slot k(0-3) -> element 4l+k ; slots 4-7 -> 128+4l+k
    sm[warp][0][lane] = a0; sm[warp][1][lane] = a1;
    sm[warp][2][lane] = a2; sm[warp][3][lane] = a3;
    sm[warp][4][lane] = a4; sm[warp][5][lane] = a5;
    sm[warp][6][lane] = a6; sm[warp][7][lane] = a7;
    __syncthreads();

    // thread t -> elements t and t+128; combine 4 warps; RED.ADD into g_sum
    {
        int t  = threadIdx.x;                 // 0..127
        int l0 = t >> 2, k0 = t & 3;
        float v0 = sm[0][k0][l0] + sm[1][k0][l0] + sm[2][k0][l0] + sm[3][k0][l0];
        float v1 = sm[0][4 + k0][l0] + sm[1][4 + k0][l0]
                 + sm[2][4 + k0][l0] + sm[3][4 + k0][l0];
        atomicAdd(&g_sum[c * D_DIM + t], v0);
        atomicAdd(&g_sum[c * D_DIM + t + 128], v1);
    }

    __threadfence();
    __syncthreads();
    if (threadIdx.x == 0) {
        int p = atomicAdd(&g_cdone[c], 1);
        s_fin = (p == NSEG - 1) ? 1 : 0;
    }
    __syncthreads();

    if (s_fin) {
        __threadfence();
        int t = threadIdx.x;
        volatile float* gs = g_sum;
        float v0 = gs[c * D_DIM + t];
        float v1 = gs[c * D_DIM + t + 128];
        g_sum[c * D_DIM + t] = 0.f;            // self-reset
        g_sum[c * D_DIM + t + 128] = 0.f;
        float ss = v0 * v0 + v1 * v1;
        #pragma unroll
        for (int o = 16; o; o >>= 1) ss += __shfl_xor_sync(0xffffffffu, ss, o);
        if (lane == 0) sm[0][0][warp] = ss;
        __syncthreads();
        if (threadIdx.x == 0) {
            float tot = sm[0][0][0] + sm[0][0][1] + sm[0][0][2] + sm[0][0][3];
            atomicAdd(&g_acc, sqrtf(tot));
            g_cnt[c * CNT_PAD] = 0;            // self-reset
            g_cdone[c]         = 0;
            __threadfence();
            unsigned q = atomicAdd(&g_done, 1u);
            if (q == (unsigned)(C_CLS - 1)) {
                __threadfence();
                float acc = *((volatile float*)&g_acc);
                out[0] = 1.0f - acc / (float)B;
                g_acc  = 0.0f;                 // global self-reset
                g_done = 0u;
            }
        }
    }
}

extern "C" void kernel_launch(void* const* d_in, const int* in_sizes, int n_in,
                              void* d_out, int out_size) {
    const float* features = (const float*)d_in[0];
    const void*  labels   = d_in[1];
    int B = in_sizes[1];                                    // 262144 labels
    if (B * D_DIM != in_sizes[0]) B = in_sizes[0] / D_DIM;  // defensive

    scatter_kernel<<<(B + 511) / 512, 512>>>(labels, B);
    class_kernel<<<C_CLS * NSEG, 128>>>(features, (float*)d_out, B);
}